// round 1
// baseline (speedup 1.0000x reference)
#include <cuda_runtime.h>
#include <math.h>

#define BB 32
#define CC 128
#define VV 64
#define TT 128
#define SP (VV*TT)   // 8192

// Scratch (device globals: allocation-free rule)
__device__ float g_buf1[(size_t)BB * 192 * SP]; // [vq16|vk16|vv64|tq16|tk16|tv64]
__device__ float g_av [(size_t)BB * CC  * SP];  // [av_v 64 | av_t 64]
__device__ float g_mean [BB * CC];
__device__ float g_scale[BB * CC];

// ---------------------------------------------------------------------------
// Conv stage 1: 192 output channels from x, tanh on q/k segments.
// Tile: 32x32 spatial, 16 out-channels per block, 8-ci chunks.
// ---------------------------------------------------------------------------
__global__ __launch_bounds__(256) void conv1_kernel(
    const float* __restrict__ x,
    const float* __restrict__ v_qw, const float* __restrict__ v_kw,
    const float* __restrict__ v_vw,
    const float* __restrict__ t_qw, const float* __restrict__ t_kw,
    const float* __restrict__ t_vw)
{
    __shared__ float xs[8][34][34];
    __shared__ float ws[16][8][9];
    const int tid = threadIdx.x;
    const int tile = blockIdx.x;          // 0..7  (2 V-tiles x 4 T-tiles)
    const int b = blockIdx.y;
    const int co0 = blockIdx.z * 16;      // 0..176
    const int v0 = (tile >> 2) * 32;
    const int t0 = (tile & 3) * 32;

    const float* wbase; int coL; bool dotanh;
    if      (co0 < 16)  { wbase = v_qw; coL = co0;        dotanh = true;  }
    else if (co0 < 32)  { wbase = v_kw; coL = co0 - 16;   dotanh = true;  }
    else if (co0 < 96)  { wbase = v_vw; coL = co0 - 32;   dotanh = false; }
    else if (co0 < 112) { wbase = t_qw; coL = co0 - 96;   dotanh = true;  }
    else if (co0 < 128) { wbase = t_kw; coL = co0 - 112;  dotanh = true;  }
    else                { wbase = t_vw; coL = co0 - 128;  dotanh = false; }

    int vl[4], tl[4];
    #pragma unroll
    for (int s = 0; s < 4; s++) { int p = tid + s*256; vl[s] = p >> 5; tl[s] = p & 31; }

    float acc[4][16];
    #pragma unroll
    for (int s = 0; s < 4; s++)
        #pragma unroll
        for (int co = 0; co < 16; co++) acc[s][co] = 0.f;

    for (int cc = 0; cc < 16; cc++) {
        const int ci0 = cc * 8;
        for (int idx = tid; idx < 8*34*34; idx += 256) {
            int ci = idx / (34*34); int rem = idx % (34*34);
            int r = rem / 34, c = rem % 34;
            int gv = v0 - 1 + r, gt = t0 - 1 + c;
            float val = 0.f;
            if (gv >= 0 && gv < VV && gt >= 0 && gt < TT)
                val = x[(((size_t)b*CC + ci0 + ci)*VV + gv)*TT + gt];
            xs[ci][r][c] = val;
        }
        for (int idx = tid; idx < 16*8*9; idx += 256) {
            int co = idx / 72; int rem = idx % 72;
            int ci = rem / 9;  int k = rem % 9;
            ws[co][ci][k] = wbase[((coL + co)*CC + ci0 + ci)*9 + k];
        }
        __syncthreads();
        #pragma unroll 1
        for (int ci = 0; ci < 8; ci++) {
            #pragma unroll
            for (int kh = 0; kh < 3; kh++)
            #pragma unroll
            for (int kw = 0; kw < 3; kw++) {
                float w[16];
                #pragma unroll
                for (int co = 0; co < 16; co++) w[co] = ws[co][ci][kh*3+kw];
                #pragma unroll
                for (int s = 0; s < 4; s++) {
                    float xv = xs[ci][vl[s]+kh][tl[s]+kw];
                    #pragma unroll
                    for (int co = 0; co < 16; co++)
                        acc[s][co] = fmaf(w[co], xv, acc[s][co]);
                }
            }
        }
        __syncthreads();
    }
    #pragma unroll
    for (int s = 0; s < 4; s++) {
        int v = v0 + vl[s], t = t0 + tl[s];
        #pragma unroll
        for (int co = 0; co < 16; co++) {
            float r = acc[s][co];
            if (dotanh) r = tanhf(r);
            g_buf1[(((size_t)b*192 + co0 + co)*VV + v)*TT + t] = r;
        }
    }
}

// ---------------------------------------------------------------------------
// V-axis attention: per (b,t). logits[v,w] = sum_c q[c,v]k[c,w]; softmax over w;
// av[c,v] = sum_w attn[v,w] v[c,w].   Channels: q 0..15, k 16..31, v 32..95.
// ---------------------------------------------------------------------------
__global__ __launch_bounds__(256) void attnV_kernel()
{
    __shared__ float Qs[16][64], Ks[16][64], Vs[64][64], L[64][65];
    const int b = blockIdx.x >> 7, t = blockIdx.x & 127;
    const int tid = threadIdx.x;
    const float* base = g_buf1 + (size_t)b * 192 * SP;

    for (int idx = tid; idx < 16*64; idx += 256) {
        int c = idx >> 6, v = idx & 63;
        Qs[c][v] = base[(size_t)c*SP + v*TT + t];
        Ks[c][v] = base[(size_t)(16+c)*SP + v*TT + t];
    }
    for (int idx = tid; idx < 64*64; idx += 256) {
        int c = idx >> 6, w = idx & 63;
        Vs[c][w] = base[(size_t)(32+c)*SP + w*TT + t];
    }
    __syncthreads();
    for (int idx = tid; idx < 64*64; idx += 256) {
        int v = idx >> 6, w = idx & 63;
        float s = 0.f;
        #pragma unroll
        for (int c = 0; c < 16; c++) s += Qs[c][v]*Ks[c][w];
        L[v][w] = s;
    }
    __syncthreads();
    if (tid < 64) {
        float m = -1e30f;
        for (int w = 0; w < 64; w++) m = fmaxf(m, L[tid][w]);
        float sum = 0.f;
        for (int w = 0; w < 64; w++) { float e = __expf(L[tid][w]-m); L[tid][w] = e; sum += e; }
        float inv = 1.f/sum;
        for (int w = 0; w < 64; w++) L[tid][w] *= inv;
    }
    __syncthreads();
    float* avb = g_av + (size_t)b * CC * SP;
    for (int idx = tid; idx < 64*64; idx += 256) {
        int c = idx >> 6, v = idx & 63;
        float s = 0.f;
        #pragma unroll
        for (int w = 0; w < 64; w++) s += L[v][w]*Vs[c][w];
        avb[(size_t)c*SP + v*TT + t] = s;
    }
}

// ---------------------------------------------------------------------------
// T-axis attention: per (b,v). logits[t,s] = sum_c q[c,t]k[c,s]; softmax over s;
// av[c,t] = sum_s attn[t,s] v[c,s].  Channels: q 96..111, k 112..127, v 128..191.
// Dynamic smem: 28800 floats (115200 B).
// ---------------------------------------------------------------------------
__global__ __launch_bounds__(256) void attnT_kernel()
{
    extern __shared__ float sm[];
    float* Qs = sm;                 // 16*128
    float* Ks = Qs + 16*128;        // 16*128
    float* Vs = Ks + 16*128;        // 64*128
    float* L  = Vs + 64*128;        // 128*129
    const int b = blockIdx.x >> 6, v = blockIdx.x & 63;
    const int tid = threadIdx.x;
    const float* base = g_buf1 + (size_t)b * 192 * SP + (size_t)v * TT;

    for (int idx = tid; idx < 16*128; idx += 256) {
        int c = idx >> 7, t = idx & 127;
        Qs[idx] = base[(size_t)(96 + c)*SP + t];
        Ks[idx] = base[(size_t)(112 + c)*SP + t];
    }
    for (int idx = tid; idx < 64*128; idx += 256) {
        int c = idx >> 7, t = idx & 127;
        Vs[idx] = base[(size_t)(128 + c)*SP + t];
    }
    __syncthreads();
    for (int idx = tid; idx < 128*128; idx += 256) {
        int t = idx >> 7, s0 = idx & 127;
        float s = 0.f;
        #pragma unroll
        for (int c = 0; c < 16; c++) s += Qs[c*128 + t]*Ks[c*128 + s0];
        L[t*129 + s0] = s;
    }
    __syncthreads();
    if (tid < 128) {
        float* row = L + tid*129;
        float m = -1e30f;
        for (int s0 = 0; s0 < 128; s0++) m = fmaxf(m, row[s0]);
        float sum = 0.f;
        for (int s0 = 0; s0 < 128; s0++) { float e = __expf(row[s0]-m); row[s0] = e; sum += e; }
        float inv = 1.f/sum;
        for (int s0 = 0; s0 < 128; s0++) row[s0] *= inv;
    }
    __syncthreads();
    float* avb = g_av + (size_t)b * CC * SP + (size_t)64 * SP + (size_t)v * TT;
    for (int idx = tid; idx < 64*128; idx += 256) {
        int c = idx >> 7, t = idx & 127;
        float s = 0.f;
        #pragma unroll
        for (int s0 = 0; s0 < 128; s0++) s += L[t*129 + s0]*Vs[c*128 + s0];
        avb[(size_t)c*SP + t] = s;
    }
}

// ---------------------------------------------------------------------------
// SE: per-(b,c) spatial mean, then tiny MLP -> sigmoid gate.
// ---------------------------------------------------------------------------
__global__ __launch_bounds__(256) void se_mean_kernel(const float* __restrict__ x)
{
    __shared__ float red[256];
    const int bc = blockIdx.x;
    const float* p = x + (size_t)bc * SP;
    float s = 0.f;
    for (int i = threadIdx.x; i < SP; i += 256) s += p[i];
    red[threadIdx.x] = s; __syncthreads();
    for (int off = 128; off > 0; off >>= 1) {
        if (threadIdx.x < off) red[threadIdx.x] += red[threadIdx.x + off];
        __syncthreads();
    }
    if (threadIdx.x == 0) g_mean[bc] = red[0] * (1.f / SP);
}

__global__ __launch_bounds__(128) void se_mlp_kernel(
    const float* __restrict__ w1, const float* __restrict__ w2)
{
    __shared__ float ym[128];
    __shared__ float h[8];
    const int b = blockIdx.x, tid = threadIdx.x;
    ym[tid] = g_mean[b*128 + tid];
    __syncthreads();
    if (tid < 8) {
        float s = 0.f;
        for (int c = 0; c < 128; c++) s += ym[c]*w1[tid*128 + c];
        h[tid] = s > 0.f ? s : 0.f;
    }
    __syncthreads();
    float s = 0.f;
    #pragma unroll
    for (int r = 0; r < 8; r++) s += h[r]*w2[tid*8 + r];
    g_scale[b*128 + tid] = 1.f/(1.f + expf(-s));
}

// ---------------------------------------------------------------------------
// Conv stage 2 + epilogue: out = (x + sv*conv(av_v,v_ow) + st*conv(av_t,t_ow)) * se
// Sigma folded into smem weights; av_v/av_t are the 128 "input channels".
// ---------------------------------------------------------------------------
__global__ __launch_bounds__(256) void conv2_kernel(
    const float* __restrict__ x,
    const float* __restrict__ v_ow, const float* __restrict__ t_ow,
    const float* __restrict__ v_sigma, const float* __restrict__ t_sigma,
    float* __restrict__ out)
{
    __shared__ float xs[8][34][34];
    __shared__ float ws[16][8][9];
    const int tid = threadIdx.x;
    const int tile = blockIdx.x;
    const int b = blockIdx.y;
    const int co0 = blockIdx.z * 16;     // 0..112
    const int v0 = (tile >> 2) * 32;
    const int t0 = (tile & 3) * 32;
    const float sv = v_sigma[0], st = t_sigma[0];

    int vl[4], tl[4];
    #pragma unroll
    for (int s = 0; s < 4; s++) { int p = tid + s*256; vl[s] = p >> 5; tl[s] = p & 31; }

    float acc[4][16];
    #pragma unroll
    for (int s = 0; s < 4; s++)
        #pragma unroll
        for (int co = 0; co < 16; co++) acc[s][co] = 0.f;

    for (int cc = 0; cc < 16; cc++) {
        const int ci0 = cc * 8;
        for (int idx = tid; idx < 8*34*34; idx += 256) {
            int ci = idx / (34*34); int rem = idx % (34*34);
            int r = rem / 34, c = rem % 34;
            int gv = v0 - 1 + r, gt = t0 - 1 + c;
            float val = 0.f;
            if (gv >= 0 && gv < VV && gt >= 0 && gt < TT)
                val = g_av[(((size_t)b*CC + ci0 + ci)*VV + gv)*TT + gt];
            xs[ci][r][c] = val;
        }
        for (int idx = tid; idx < 16*8*9; idx += 256) {
            int co = idx / 72; int rem = idx % 72;
            int ci = rem / 9;  int k = rem % 9;
            int cig = ci0 + ci;
            float wv;
            if (cig < 64) wv = v_ow[((co0 + co)*64 + cig)*9 + k] * sv;
            else          wv = t_ow[((co0 + co)*64 + (cig - 64))*9 + k] * st;
            ws[co][ci][k] = wv;
        }
        __syncthreads();
        #pragma unroll 1
        for (int ci = 0; ci < 8; ci++) {
            #pragma unroll
            for (int kh = 0; kh < 3; kh++)
            #pragma unroll
            for (int kw = 0; kw < 3; kw++) {
                float w[16];
                #pragma unroll
                for (int co = 0; co < 16; co++) w[co] = ws[co][ci][kh*3+kw];
                #pragma unroll
                for (int s = 0; s < 4; s++) {
                    float xv = xs[ci][vl[s]+kh][tl[s]+kw];
                    #pragma unroll
                    for (int co = 0; co < 16; co++)
                        acc[s][co] = fmaf(w[co], xv, acc[s][co]);
                }
            }
        }
        __syncthreads();
    }
    #pragma unroll
    for (int s = 0; s < 4; s++) {
        int v = v0 + vl[s], t = t0 + tl[s];
        #pragma unroll
        for (int co = 0; co < 16; co++) {
            size_t idx = (((size_t)b*CC + co0 + co)*VV + v)*TT + t;
            out[idx] = (x[idx] + acc[s][co]) * g_scale[b*128 + co0 + co];
        }
    }
}

// ---------------------------------------------------------------------------
extern "C" void kernel_launch(void* const* d_in, const int* in_sizes, int n_in,
                              void* d_out, int out_size)
{
    const float* x     = (const float*)d_in[0];
    const float* v_qw  = (const float*)d_in[1];
    const float* v_kw  = (const float*)d_in[2];
    const float* v_vw  = (const float*)d_in[3];
    const float* v_ow  = (const float*)d_in[4];
    const float* v_sig = (const float*)d_in[5];
    const float* t_qw  = (const float*)d_in[6];
    const float* t_kw  = (const float*)d_in[7];
    const float* t_vw  = (const float*)d_in[8];
    const float* t_ow  = (const float*)d_in[9];
    const float* t_sig = (const float*)d_in[10];
    const float* se_w1 = (const float*)d_in[11];
    const float* se_w2 = (const float*)d_in[12];
    float* out = (float*)d_out;

    const int attnT_smem = (16*128 + 16*128 + 64*128 + 128*129) * 4; // 115200 B
    cudaFuncSetAttribute(attnT_kernel, cudaFuncAttributeMaxDynamicSharedMemorySize, attnT_smem);

    conv1_kernel<<<dim3(8, 32, 12), 256>>>(x, v_qw, v_kw, v_vw, t_qw, t_kw, t_vw);
    se_mean_kernel<<<BB*CC, 256>>>(x);
    se_mlp_kernel<<<BB, 128>>>(se_w1, se_w2);
    attnV_kernel<<<BB*TT, 256>>>();
    attnT_kernel<<<BB*VV, 256, attnT_smem>>>();
    conv2_kernel<<<dim3(8, 32, 8), 256>>>(x, v_ow, t_ow, v_sig, t_sig, out);
}

// round 2
// speedup vs baseline: 1.3267x; 1.3267x over previous
#include <cuda_runtime.h>
#include <math.h>
#include <stdint.h>

#define BB 32
#define CC 128
#define VV 64
#define TT 128
#define SP (VV*TT)   // 8192

// Scratch (device globals: allocation-free rule)
__device__ float g_buf1[(size_t)BB * 192 * SP]; // [vq16|vk16|vv64|tq16|tk16|tv64]
__device__ float g_av [(size_t)BB * CC  * SP];  // [av_v 64 | av_t 64]
__device__ float g_mean [BB * CC];
__device__ float g_scale[BB * CC];

// ---------------------------------------------------------------------------
// TF32 helpers
// ---------------------------------------------------------------------------
__device__ __forceinline__ uint32_t f2tf32(float f) {
    uint32_t r;
    asm("cvt.rna.tf32.f32 %0, %1;" : "=r"(r) : "f"(f));
    return r;
}

__device__ __forceinline__ void mma_tf32(
    float& d0, float& d1, float& d2, float& d3,
    uint32_t a0, uint32_t a1, uint32_t a2, uint32_t a3,
    uint32_t b0, uint32_t b1)
{
    asm volatile(
        "mma.sync.aligned.m16n8k8.row.col.f32.tf32.tf32.f32 "
        "{%0,%1,%2,%3}, {%4,%5,%6,%7}, {%8,%9}, {%0,%1,%2,%3};"
        : "+f"(d0), "+f"(d1), "+f"(d2), "+f"(d3)
        : "r"(a0), "r"(a1), "r"(a2), "r"(a3), "r"(b0), "r"(b1));
}

// ---------------------------------------------------------------------------
// Conv stage 1 (tensor cores): 192 out channels from x, tanh on q/k segments.
// Implicit GEMM: D[co, pos] = sum_{tap, ci} W[co][ci,tap] * X[ci][pos+shift(tap)]
// Block: 64 co x 128 positions (4v x 32t). 8 warps = 2(M) x 4(N).
// Warp tile 32x32 -> 2 m16 x 4 n8 mma tiles. K in chunks of 8 ci, 9 taps.
// ---------------------------------------------------------------------------
__global__ __launch_bounds__(256) void conv1_mma_kernel(
    const float* __restrict__ x,
    const float* __restrict__ v_qw, const float* __restrict__ v_kw,
    const float* __restrict__ v_vw,
    const float* __restrict__ t_qw, const float* __restrict__ t_kw,
    const float* __restrict__ t_vw)
{
    __shared__ uint32_t xs[8][6][36];     // [ci][v-halo][t-halo(34 used)] tf32 bits
    __shared__ uint32_t ws[9][8][64];     // [tap][ci][co] tf32 bits

    const int tid = threadIdx.x;
    const int lane = tid & 31;
    const int warp = tid >> 5;
    const int g  = lane >> 2;     // 0..7
    const int k4 = lane & 3;      // 0..3
    const int wm = warp >> 2;     // 0..1 (M)
    const int wn = warp & 3;      // 0..3 (N = v row)

    const int tile = blockIdx.x;          // 64 tiles: 16 v-tiles x 4 t-tiles
    const int b = blockIdx.y;
    const int co0 = blockIdx.z * 64;      // 0,64,128
    const int v0 = (tile >> 2) * 4;
    const int t0 = (tile & 3) * 32;

    float acc[2][4][4];
    #pragma unroll
    for (int mt = 0; mt < 2; mt++)
        #pragma unroll
        for (int nt = 0; nt < 4; nt++)
            #pragma unroll
            for (int r = 0; r < 4; r++) acc[mt][nt][r] = 0.f;

    for (int cc = 0; cc < 16; cc++) {
        const int ci0 = cc * 8;
        // ---- fill xs (1728 elems) ----
        for (int idx = tid; idx < 8*6*36; idx += 256) {
            int ci = idx / 216; int rem = idx % 216;
            int r = rem / 36, c = rem % 36;
            if (c < 34) {
                int gv = v0 - 1 + r, gt = t0 - 1 + c;
                float val = 0.f;
                if (gv >= 0 && gv < VV && gt >= 0 && gt < TT)
                    val = x[(((size_t)b*CC + ci0 + ci)*VV + gv)*TT + gt];
                xs[ci][r][c] = f2tf32(val);
            }
        }
        // ---- fill ws (4608 elems), coalesced 72-float runs per co ----
        for (int idx = tid; idx < 64*72; idx += 256) {
            int co = idx / 72; int j = idx % 72;   // j = ci_local*9 + tap
            int coG = co0 + co;
            const float* wbase; int coL;
            if      (coG < 16)  { wbase = v_qw; coL = coG;       }
            else if (coG < 32)  { wbase = v_kw; coL = coG - 16;  }
            else if (coG < 96)  { wbase = v_vw; coL = coG - 32;  }
            else if (coG < 112) { wbase = t_qw; coL = coG - 96;  }
            else if (coG < 128) { wbase = t_kw; coL = coG - 112; }
            else                { wbase = t_vw; coL = coG - 128; }
            float wv = wbase[(size_t)coL*CC*9 + ci0*9 + j];
            ws[j % 9][j / 9][co] = f2tf32(wv);
        }
        __syncthreads();

        // ---- compute: 9 taps x 8 mma per warp ----
        #pragma unroll
        for (int kh = 0; kh < 3; kh++) {
            #pragma unroll
            for (int kw = 0; kw < 3; kw++) {
                const int tap = kh*3 + kw;
                uint32_t a[2][4];
                #pragma unroll
                for (int mt = 0; mt < 2; mt++) {
                    int cb = wm*32 + mt*16 + g;
                    a[mt][0] = ws[tap][k4  ][cb];
                    a[mt][1] = ws[tap][k4  ][cb+8];
                    a[mt][2] = ws[tap][k4+4][cb];
                    a[mt][3] = ws[tap][k4+4][cb+8];
                }
                #pragma unroll
                for (int nt = 0; nt < 4; nt++) {
                    uint32_t b0 = xs[k4  ][wn+kh][nt*8 + g + kw];
                    uint32_t b1 = xs[k4+4][wn+kh][nt*8 + g + kw];
                    #pragma unroll
                    for (int mt = 0; mt < 2; mt++)
                        mma_tf32(acc[mt][nt][0], acc[mt][nt][1],
                                 acc[mt][nt][2], acc[mt][nt][3],
                                 a[mt][0], a[mt][1], a[mt][2], a[mt][3], b0, b1);
                }
            }
        }
        __syncthreads();
    }

    // ---- store: float2 per (c0,c1) and (c2,c3) pair, tanh on q/k channels ----
    const int v = v0 + wn;
    #pragma unroll
    for (int mt = 0; mt < 2; mt++) {
        #pragma unroll
        for (int nt = 0; nt < 4; nt++) {
            int coA = co0 + wm*32 + mt*16 + g;
            int coB = coA + 8;
            int t = t0 + nt*8 + k4*2;
            bool tA = (coA < 32) || (coA >= 96 && coA < 128);
            bool tB = (coB < 32) || (coB >= 96 && coB < 128);
            float r0 = acc[mt][nt][0], r1 = acc[mt][nt][1];
            float r2 = acc[mt][nt][2], r3 = acc[mt][nt][3];
            if (tA) { r0 = tanhf(r0); r1 = tanhf(r1); }
            if (tB) { r2 = tanhf(r2); r3 = tanhf(r3); }
            float2* pA = (float2*)&g_buf1[(((size_t)b*192 + coA)*VV + v)*TT + t];
            float2* pB = (float2*)&g_buf1[(((size_t)b*192 + coB)*VV + v)*TT + t];
            *pA = make_float2(r0, r1);
            *pB = make_float2(r2, r3);
        }
    }
}

// ---------------------------------------------------------------------------
// Conv stage 2 (tensor cores) + epilogue:
// out = (x + conv(g_av, [v_ow*sv | t_ow*st])) * se_scale
// ---------------------------------------------------------------------------
__global__ __launch_bounds__(256) void conv2_mma_kernel(
    const float* __restrict__ x,
    const float* __restrict__ v_ow, const float* __restrict__ t_ow,
    const float* __restrict__ v_sigma, const float* __restrict__ t_sigma,
    float* __restrict__ out)
{
    __shared__ uint32_t xs[8][6][36];
    __shared__ uint32_t ws[9][8][64];

    const int tid = threadIdx.x;
    const int lane = tid & 31;
    const int warp = tid >> 5;
    const int g  = lane >> 2;
    const int k4 = lane & 3;
    const int wm = warp >> 2;
    const int wn = warp & 3;

    const int tile = blockIdx.x;
    const int b = blockIdx.y;
    const int co0 = blockIdx.z * 64;      // 0,64
    const int v0 = (tile >> 2) * 4;
    const int t0 = (tile & 3) * 32;
    const float sv = v_sigma[0], st = t_sigma[0];

    float acc[2][4][4];
    #pragma unroll
    for (int mt = 0; mt < 2; mt++)
        #pragma unroll
        for (int nt = 0; nt < 4; nt++)
            #pragma unroll
            for (int r = 0; r < 4; r++) acc[mt][nt][r] = 0.f;

    for (int cc = 0; cc < 16; cc++) {
        const int ci0 = cc * 8;
        for (int idx = tid; idx < 8*6*36; idx += 256) {
            int ci = idx / 216; int rem = idx % 216;
            int r = rem / 36, c = rem % 36;
            if (c < 34) {
                int gv = v0 - 1 + r, gt = t0 - 1 + c;
                float val = 0.f;
                if (gv >= 0 && gv < VV && gt >= 0 && gt < TT)
                    val = g_av[(((size_t)b*CC + ci0 + ci)*VV + gv)*TT + gt];
                xs[ci][r][c] = f2tf32(val);
            }
        }
        for (int idx = tid; idx < 64*72; idx += 256) {
            int co = idx / 72; int j = idx % 72;
            int coG = co0 + co;
            float wv;
            if (ci0 < 64) wv = v_ow[(size_t)coG*64*9 + ci0*9 + j] * sv;
            else          wv = t_ow[(size_t)coG*64*9 + (ci0-64)*9 + j] * st;
            ws[j % 9][j / 9][co] = f2tf32(wv);
        }
        __syncthreads();

        #pragma unroll
        for (int kh = 0; kh < 3; kh++) {
            #pragma unroll
            for (int kw = 0; kw < 3; kw++) {
                const int tap = kh*3 + kw;
                uint32_t a[2][4];
                #pragma unroll
                for (int mt = 0; mt < 2; mt++) {
                    int cb = wm*32 + mt*16 + g;
                    a[mt][0] = ws[tap][k4  ][cb];
                    a[mt][1] = ws[tap][k4  ][cb+8];
                    a[mt][2] = ws[tap][k4+4][cb];
                    a[mt][3] = ws[tap][k4+4][cb+8];
                }
                #pragma unroll
                for (int nt = 0; nt < 4; nt++) {
                    uint32_t b0 = xs[k4  ][wn+kh][nt*8 + g + kw];
                    uint32_t b1 = xs[k4+4][wn+kh][nt*8 + g + kw];
                    #pragma unroll
                    for (int mt = 0; mt < 2; mt++)
                        mma_tf32(acc[mt][nt][0], acc[mt][nt][1],
                                 acc[mt][nt][2], acc[mt][nt][3],
                                 a[mt][0], a[mt][1], a[mt][2], a[mt][3], b0, b1);
                }
            }
        }
        __syncthreads();
    }

    const int v = v0 + wn;
    #pragma unroll
    for (int mt = 0; mt < 2; mt++) {
        #pragma unroll
        for (int nt = 0; nt < 4; nt++) {
            int coA = co0 + wm*32 + mt*16 + g;
            int coB = coA + 8;
            int t = t0 + nt*8 + k4*2;
            size_t iA = (((size_t)b*CC + coA)*VV + v)*TT + t;
            size_t iB = (((size_t)b*CC + coB)*VV + v)*TT + t;
            float2 xA = *(const float2*)&x[iA];
            float2 xB = *(const float2*)&x[iB];
            float sA = g_scale[b*CC + coA];
            float sB = g_scale[b*CC + coB];
            *(float2*)&out[iA] = make_float2((xA.x + acc[mt][nt][0]) * sA,
                                             (xA.y + acc[mt][nt][1]) * sA);
            *(float2*)&out[iB] = make_float2((xB.x + acc[mt][nt][2]) * sB,
                                             (xB.y + acc[mt][nt][3]) * sB);
        }
    }
}

// ---------------------------------------------------------------------------
// V-axis attention: per (b,t). Channels: q 0..15, k 16..31, v 32..95.
// ---------------------------------------------------------------------------
__global__ __launch_bounds__(256) void attnV_kernel()
{
    __shared__ float Qs[16][64], Ks[16][64], Vs[64][64], L[64][65];
    const int b = blockIdx.x >> 7, t = blockIdx.x & 127;
    const int tid = threadIdx.x;
    const float* base = g_buf1 + (size_t)b * 192 * SP;

    for (int idx = tid; idx < 16*64; idx += 256) {
        int c = idx >> 6, v = idx & 63;
        Qs[c][v] = base[(size_t)c*SP + v*TT + t];
        Ks[c][v] = base[(size_t)(16+c)*SP + v*TT + t];
    }
    for (int idx = tid; idx < 64*64; idx += 256) {
        int c = idx >> 6, w = idx & 63;
        Vs[c][w] = base[(size_t)(32+c)*SP + w*TT + t];
    }
    __syncthreads();
    for (int idx = tid; idx < 64*64; idx += 256) {
        int v = idx >> 6, w = idx & 63;
        float s = 0.f;
        #pragma unroll
        for (int c = 0; c < 16; c++) s += Qs[c][v]*Ks[c][w];
        L[v][w] = s;
    }
    __syncthreads();
    if (tid < 64) {
        float m = -1e30f;
        for (int w = 0; w < 64; w++) m = fmaxf(m, L[tid][w]);
        float sum = 0.f;
        for (int w = 0; w < 64; w++) { float e = __expf(L[tid][w]-m); L[tid][w] = e; sum += e; }
        float inv = 1.f/sum;
        for (int w = 0; w < 64; w++) L[tid][w] *= inv;
    }
    __syncthreads();
    float* avb = g_av + (size_t)b * CC * SP;
    for (int idx = tid; idx < 64*64; idx += 256) {
        int c = idx >> 6, v = idx & 63;
        float s = 0.f;
        #pragma unroll
        for (int w = 0; w < 64; w++) s += L[v][w]*Vs[c][w];
        avb[(size_t)c*SP + v*TT + t] = s;
    }
}

// ---------------------------------------------------------------------------
// T-axis attention: per (b,v). Channels: q 96..111, k 112..127, v 128..191.
// ---------------------------------------------------------------------------
__global__ __launch_bounds__(256) void attnT_kernel()
{
    extern __shared__ float sm[];
    float* Qs = sm;                 // 16*128
    float* Ks = Qs + 16*128;        // 16*128
    float* Vs = Ks + 16*128;        // 64*128
    float* L  = Vs + 64*128;        // 128*129
    const int b = blockIdx.x >> 6, v = blockIdx.x & 63;
    const int tid = threadIdx.x;
    const float* base = g_buf1 + (size_t)b * 192 * SP + (size_t)v * TT;

    for (int idx = tid; idx < 16*128; idx += 256) {
        int c = idx >> 7, t = idx & 127;
        Qs[idx] = base[(size_t)(96 + c)*SP + t];
        Ks[idx] = base[(size_t)(112 + c)*SP + t];
    }
    for (int idx = tid; idx < 64*128; idx += 256) {
        int c = idx >> 7, t = idx & 127;
        Vs[idx] = base[(size_t)(128 + c)*SP + t];
    }
    __syncthreads();
    for (int idx = tid; idx < 128*128; idx += 256) {
        int t = idx >> 7, s0 = idx & 127;
        float s = 0.f;
        #pragma unroll
        for (int c = 0; c < 16; c++) s += Qs[c*128 + t]*Ks[c*128 + s0];
        L[t*129 + s0] = s;
    }
    __syncthreads();
    if (tid < 128) {
        float* row = L + tid*129;
        float m = -1e30f;
        for (int s0 = 0; s0 < 128; s0++) m = fmaxf(m, row[s0]);
        float sum = 0.f;
        for (int s0 = 0; s0 < 128; s0++) { float e = __expf(row[s0]-m); row[s0] = e; sum += e; }
        float inv = 1.f/sum;
        for (int s0 = 0; s0 < 128; s0++) row[s0] *= inv;
    }
    __syncthreads();
    float* avb = g_av + (size_t)b * CC * SP + (size_t)64 * SP + (size_t)v * TT;
    for (int idx = tid; idx < 64*128; idx += 256) {
        int c = idx >> 7, t = idx & 127;
        float s = 0.f;
        #pragma unroll
        for (int s0 = 0; s0 < 128; s0++) s += L[t*129 + s0]*Vs[c*128 + s0];
        avb[(size_t)c*SP + t] = s;
    }
}

// ---------------------------------------------------------------------------
// SE: per-(b,c) spatial mean, then tiny MLP -> sigmoid gate.
// ---------------------------------------------------------------------------
__global__ __launch_bounds__(256) void se_mean_kernel(const float* __restrict__ x)
{
    __shared__ float red[256];
    const int bc = blockIdx.x;
    const float* p = x + (size_t)bc * SP;
    float s = 0.f;
    for (int i = threadIdx.x; i < SP; i += 256) s += p[i];
    red[threadIdx.x] = s; __syncthreads();
    for (int off = 128; off > 0; off >>= 1) {
        if (threadIdx.x < off) red[threadIdx.x] += red[threadIdx.x + off];
        __syncthreads();
    }
    if (threadIdx.x == 0) g_mean[bc] = red[0] * (1.f / SP);
}

__global__ __launch_bounds__(128) void se_mlp_kernel(
    const float* __restrict__ w1, const float* __restrict__ w2)
{
    __shared__ float ym[128];
    __shared__ float h[8];
    const int b = blockIdx.x, tid = threadIdx.x;
    ym[tid] = g_mean[b*128 + tid];
    __syncthreads();
    if (tid < 8) {
        float s = 0.f;
        for (int c = 0; c < 128; c++) s += ym[c]*w1[tid*128 + c];
        h[tid] = s > 0.f ? s : 0.f;
    }
    __syncthreads();
    float s = 0.f;
    #pragma unroll
    for (int r = 0; r < 8; r++) s += h[r]*w2[tid*8 + r];
    g_scale[b*128 + tid] = 1.f/(1.f + expf(-s));
}

// ---------------------------------------------------------------------------
extern "C" void kernel_launch(void* const* d_in, const int* in_sizes, int n_in,
                              void* d_out, int out_size)
{
    const float* x     = (const float*)d_in[0];
    const float* v_qw  = (const float*)d_in[1];
    const float* v_kw  = (const float*)d_in[2];
    const float* v_vw  = (const float*)d_in[3];
    const float* v_ow  = (const float*)d_in[4];
    const float* v_sig = (const float*)d_in[5];
    const float* t_qw  = (const float*)d_in[6];
    const float* t_kw  = (const float*)d_in[7];
    const float* t_vw  = (const float*)d_in[8];
    const float* t_ow  = (const float*)d_in[9];
    const float* t_sig = (const float*)d_in[10];
    const float* se_w1 = (const float*)d_in[11];
    const float* se_w2 = (const float*)d_in[12];
    float* out = (float*)d_out;

    const int attnT_smem = (16*128 + 16*128 + 64*128 + 128*129) * 4; // 115200 B
    cudaFuncSetAttribute(attnT_kernel, cudaFuncAttributeMaxDynamicSharedMemorySize, attnT_smem);

    conv1_mma_kernel<<<dim3(64, 32, 3), 256>>>(x, v_qw, v_kw, v_vw, t_qw, t_kw, t_vw);
    se_mean_kernel<<<BB*CC, 256>>>(x);
    se_mlp_kernel<<<BB, 128>>>(se_w1, se_w2);
    attnV_kernel<<<BB*TT, 256>>>();
    attnT_kernel<<<BB*VV, 256, attnT_smem>>>();
    conv2_mma_kernel<<<dim3(64, 32, 2), 256>>>(x, v_ow, t_ow, v_sig, t_sig, out);
}

// round 5
// speedup vs baseline: 3.9613x; 2.9858x over previous
#include <cuda_runtime.h>
#include <cuda_bf16.h>
#include <math.h>
#include <stdint.h>

#define BB 32
#define CC 128
#define VV 64
#define TT 128
#define SP (VV*TT)   // 8192

// ---------------------------------------------------------------------------
// Scratch (device globals) — EXACTLY the R2-proven footprint + 1.1 MiB weights.
// ---------------------------------------------------------------------------
__device__ float g_buf1[(size_t)BB * 192 * SP]; // conv1 out [b][c][v][t]  192 MiB
__device__ float g_av [(size_t)BB * CC  * SP];  // [av_v 64 | av_t 64]     128 MiB
__device__ float g_mean [BB * CC];
__device__ float g_scale[BB * CC];
// packed bf16 weights: [chunk8][tap9][co][12 words] (words 0..7 = ci-pairs, 8..11 pad)
__device__ uint32_t g_w1[8 * 9 * 192 * 12];
__device__ uint32_t g_w2[8 * 9 * 128 * 12];

// ---------------------------------------------------------------------------
__device__ __forceinline__ uint32_t pack_bf16(float a, float b) {
    __nv_bfloat16 lo = __float2bfloat16(a), hi = __float2bfloat16(b);
    return ((uint32_t)__bfloat16_as_ushort(hi) << 16) | (uint32_t)__bfloat16_as_ushort(lo);
}

__device__ __forceinline__ void mma_bf16(
    float& d0, float& d1, float& d2, float& d3,
    uint32_t a0, uint32_t a1, uint32_t a2, uint32_t a3,
    uint32_t b0, uint32_t b1)
{
    asm volatile(
        "mma.sync.aligned.m16n8k16.row.col.f32.bf16.bf16.f32 "
        "{%0,%1,%2,%3}, {%4,%5,%6,%7}, {%8,%9}, {%0,%1,%2,%3};"
        : "+f"(d0), "+f"(d1), "+f"(d2), "+f"(d3)
        : "r"(a0), "r"(a1), "r"(a2), "r"(a3), "r"(b0), "r"(b1));
}

// ---------------------------------------------------------------------------
// Weight pre-conversion kernels
// ---------------------------------------------------------------------------
__global__ __launch_bounds__(256) void wcvt1_kernel(
    const float* __restrict__ v_qw, const float* __restrict__ v_kw,
    const float* __restrict__ v_vw,
    const float* __restrict__ t_qw, const float* __restrict__ t_kw,
    const float* __restrict__ t_vw)
{
    int idx = blockIdx.x * 256 + threadIdx.x;
    if (idx >= 8*9*192*12) return;
    int w    = idx % 12;
    int co   = (idx / 12) % 192;
    int tap  = (idx / (12*192)) % 9;
    int chunk= idx / (12*192*9);
    uint32_t val = 0;
    if (w < 8) {
        int ci = chunk*16 + w*2;
        const float* wb; int coL;
        if      (co < 16)  { wb = v_qw; coL = co;       }
        else if (co < 32)  { wb = v_kw; coL = co - 16;  }
        else if (co < 96)  { wb = v_vw; coL = co - 32;  }
        else if (co < 112) { wb = t_qw; coL = co - 96;  }
        else if (co < 128) { wb = t_kw; coL = co - 112; }
        else               { wb = t_vw; coL = co - 128; }
        float f0 = wb[(coL*CC + ci    )*9 + tap];
        float f1 = wb[(coL*CC + ci + 1)*9 + tap];
        val = pack_bf16(f0, f1);
    }
    g_w1[idx] = val;
}

__global__ __launch_bounds__(256) void wcvt2_kernel(
    const float* __restrict__ v_ow, const float* __restrict__ t_ow,
    const float* __restrict__ v_sigma, const float* __restrict__ t_sigma)
{
    int idx = blockIdx.x * 256 + threadIdx.x;
    if (idx >= 8*9*128*12) return;
    int w    = idx % 12;
    int co   = (idx / 12) % 128;
    int tap  = (idx / (12*128)) % 9;
    int chunk= idx / (12*128*9);
    uint32_t val = 0;
    if (w < 8) {
        int ci = chunk*16 + w*2;
        float f0, f1;
        if (ci < 64) {
            float s = v_sigma[0];
            f0 = v_ow[(co*64 + ci    )*9 + tap] * s;
            f1 = v_ow[(co*64 + ci + 1)*9 + tap] * s;
        } else {
            float s = t_sigma[0];
            f0 = t_ow[(co*64 + (ci-64))*9 + tap] * s;
            f1 = t_ow[(co*64 + (ci-63))*9 + tap] * s;
        }
        val = pack_bf16(f0, f1);
    }
    g_w2[idx] = val;
}

// ---------------------------------------------------------------------------
// bf16 implicit-GEMM conv core. R2-proven geometry:
// Block: 64 co x 128 pos (4v x 32t). 8 warps = 2(M co) x 4(N v-row).
// Warp tile 32co x 32t -> acc[2][4][4] = 32 regs. m16n8k16, 8 ci-chunks of 16.
// xs: [6 v][34 t][12 words(ci-pair + pad)] ; ws: [9 tap][64 co][12 words]
// ---------------------------------------------------------------------------
__device__ __forceinline__ void conv_core_f(
    const float* __restrict__ src,        // [b][128][v][t]
    const uint32_t* __restrict__ gw,      // packed weights, co-dim = CO_TOT
    int CO_TOT,
    int b, int co0, int v0, int t0,
    float acc[2][4][4])
{
    __shared__ uint32_t xs[6*34*12];      // 9792 B
    __shared__ uint32_t ws[9*64*12];      // 27648 B

    const int tid  = threadIdx.x;
    const int lane = tid & 31;
    const int warp = tid >> 5;
    const int g  = lane >> 2;
    const int k4 = lane & 3;
    const int wm = warp >> 2;
    const int wn = warp & 3;

    #pragma unroll
    for (int mt = 0; mt < 2; mt++)
        #pragma unroll
        for (int nt = 0; nt < 4; nt++)
            #pragma unroll
            for (int r = 0; r < 4; r++) acc[mt][nt][r] = 0.f;

    for (int chunk = 0; chunk < 8; chunk++) {
        // ---- fill xs: 6v x 8cp x 34t = 1632 packed words ----
        for (int idx = tid; idx < 1632; idx += 256) {
            int v   = idx / 272;          // 8*34
            int rem = idx % 272;
            int cp  = rem / 34;
            int t   = rem % 34;
            int gv = v0 - 1 + v, gt = t0 - 1 + t;
            int ci = chunk*16 + cp*2;
            uint32_t val = 0;
            if (gv >= 0 && gv < VV && gt >= 0 && gt < TT) {
                const float* p = src + (((size_t)b*CC + ci)*VV + gv)*TT + gt;
                val = pack_bf16(p[0], p[SP]);
            }
            xs[(v*34 + t)*12 + cp] = val;
        }
        // ---- fill ws: raw uint4 copy (1728 uint4) ----
        {
            const uint4* src4 = (const uint4*)gw;
            uint4* dst4 = (uint4*)ws;
            for (int idx = tid; idx < 1728; idx += 256) {
                int tap = idx / 192;
                int w4  = idx % 192;
                dst4[tap*192 + w4] = src4[(size_t)((chunk*9 + tap)*CO_TOT + co0)*3 + w4];
            }
        }
        __syncthreads();

        // ---- compute: 9 taps x (2mt x 4nt) MMAs ----
        #pragma unroll
        for (int kh = 0; kh < 3; kh++) {
            #pragma unroll
            for (int kw = 0; kw < 3; kw++) {
                const int tap = kh*3 + kw;
                const uint32_t* wt = ws + tap*768;
                uint32_t a0[2], a1[2], a2[2], a3[2];
                #pragma unroll
                for (int mt = 0; mt < 2; mt++) {
                    const uint32_t* p = wt + (wm*32 + mt*16 + g) * 12;
                    a0[mt] = p[k4];
                    a2[mt] = p[k4+4];
                    a1[mt] = p[96 + k4];       // +8 co rows
                    a3[mt] = p[96 + k4+4];
                }
                const uint32_t* xrow = xs + ((wn + kh)*34 + g + kw) * 12;
                #pragma unroll
                for (int nt = 0; nt < 4; nt++) {
                    const uint32_t* xr = xrow + nt*96;   // +8 t
                    uint32_t b0 = xr[k4];
                    uint32_t b1 = xr[k4+4];
                    #pragma unroll
                    for (int mt = 0; mt < 2; mt++)
                        mma_bf16(acc[mt][nt][0], acc[mt][nt][1],
                                 acc[mt][nt][2], acc[mt][nt][3],
                                 a0[mt], a1[mt], a2[mt], a3[mt], b0, b1);
                }
            }
        }
        __syncthreads();
    }
}

// ---------------------------------------------------------------------------
__global__ __launch_bounds__(256) void conv1_mma_kernel(const float* __restrict__ x)
{
    const int tile = blockIdx.x;           // 64 tiles: 16 v-tiles x 4 t-tiles
    const int b = blockIdx.y;
    const int co0 = blockIdx.z * 64;       // 0,64,128
    const int v0 = (tile >> 2) * 4;
    const int t0 = (tile & 3) * 32;

    float acc[2][4][4];
    conv_core_f(x, g_w1, 192, b, co0, v0, t0, acc);

    const int lane = threadIdx.x & 31;
    const int warp = threadIdx.x >> 5;
    const int g  = lane >> 2;
    const int k4 = lane & 3;
    const int wm = warp >> 2;
    const int wn = warp & 3;
    const int v = v0 + wn;

    #pragma unroll
    for (int mt = 0; mt < 2; mt++) {
        #pragma unroll
        for (int nt = 0; nt < 4; nt++) {
            int coA = co0 + wm*32 + mt*16 + g;
            int coB = coA + 8;
            int t = t0 + nt*8 + k4*2;
            bool tA = (coA < 32) || (coA >= 96 && coA < 128);
            bool tB = (coB < 32) || (coB >= 96 && coB < 128);
            float r0 = acc[mt][nt][0], r1 = acc[mt][nt][1];
            float r2 = acc[mt][nt][2], r3 = acc[mt][nt][3];
            if (tA) { r0 = tanhf(r0); r1 = tanhf(r1); }
            if (tB) { r2 = tanhf(r2); r3 = tanhf(r3); }
            *(float2*)&g_buf1[(((size_t)b*192 + coA)*VV + v)*TT + t] = make_float2(r0, r1);
            *(float2*)&g_buf1[(((size_t)b*192 + coB)*VV + v)*TT + t] = make_float2(r2, r3);
        }
    }
}

__global__ __launch_bounds__(256) void conv2_mma_kernel(
    const float* __restrict__ x, float* __restrict__ out)
{
    const int tile = blockIdx.x;
    const int b = blockIdx.y;
    const int co0 = blockIdx.z * 64;       // 0,64
    const int v0 = (tile >> 2) * 4;
    const int t0 = (tile & 3) * 32;

    float acc[2][4][4];
    conv_core_f(g_av, g_w2, 128, b, co0, v0, t0, acc);

    const int lane = threadIdx.x & 31;
    const int warp = threadIdx.x >> 5;
    const int g  = lane >> 2;
    const int k4 = lane & 3;
    const int wm = warp >> 2;
    const int wn = warp & 3;
    const int v = v0 + wn;

    #pragma unroll
    for (int mt = 0; mt < 2; mt++) {
        #pragma unroll
        for (int nt = 0; nt < 4; nt++) {
            int coA = co0 + wm*32 + mt*16 + g;
            int coB = coA + 8;
            int t = t0 + nt*8 + k4*2;
            size_t iA = (((size_t)b*CC + coA)*VV + v)*TT + t;
            size_t iB = (((size_t)b*CC + coB)*VV + v)*TT + t;
            float2 xA = *(const float2*)&x[iA];
            float2 xB = *(const float2*)&x[iB];
            float sA = g_scale[b*CC + coA];
            float sB = g_scale[b*CC + coB];
            *(float2*)&out[iA] = make_float2((xA.x + acc[mt][nt][0])*sA,
                                             (xA.y + acc[mt][nt][1])*sA);
            *(float2*)&out[iB] = make_float2((xB.x + acc[mt][nt][2])*sB,
                                             (xB.y + acc[mt][nt][3])*sB);
        }
    }
}

// ---------------------------------------------------------------------------
// V-axis attention: per (b,t). Channels: q 0..15, k 16..31, v 32..95. (R2 verbatim)
// ---------------------------------------------------------------------------
__global__ __launch_bounds__(256) void attnV_kernel()
{
    __shared__ float Qs[16][64], Ks[16][64], Vs[64][64], L[64][65];
    const int b = blockIdx.x >> 7, t = blockIdx.x & 127;
    const int tid = threadIdx.x;
    const float* base = g_buf1 + (size_t)b * 192 * SP;

    for (int idx = tid; idx < 16*64; idx += 256) {
        int c = idx >> 6, v = idx & 63;
        Qs[c][v] = base[(size_t)c*SP + v*TT + t];
        Ks[c][v] = base[(size_t)(16+c)*SP + v*TT + t];
    }
    for (int idx = tid; idx < 64*64; idx += 256) {
        int c = idx >> 6, w = idx & 63;
        Vs[c][w] = base[(size_t)(32+c)*SP + w*TT + t];
    }
    __syncthreads();
    for (int idx = tid; idx < 64*64; idx += 256) {
        int v = idx >> 6, w = idx & 63;
        float s = 0.f;
        #pragma unroll
        for (int c = 0; c < 16; c++) s += Qs[c][v]*Ks[c][w];
        L[v][w] = s;
    }
    __syncthreads();
    if (tid < 64) {
        float m = -1e30f;
        for (int w = 0; w < 64; w++) m = fmaxf(m, L[tid][w]);
        float sum = 0.f;
        for (int w = 0; w < 64; w++) { float e = __expf(L[tid][w]-m); L[tid][w] = e; sum += e; }
        float inv = 1.f/sum;
        for (int w = 0; w < 64; w++) L[tid][w] *= inv;
    }
    __syncthreads();
    float* avb = g_av + (size_t)b * CC * SP;
    for (int idx = tid; idx < 64*64; idx += 256) {
        int c = idx >> 6, v = idx & 63;
        float s = 0.f;
        #pragma unroll
        for (int w = 0; w < 64; w++) s += L[v][w]*Vs[c][w];
        avb[(size_t)c*SP + v*TT + t] = s;
    }
}

// ---------------------------------------------------------------------------
// T-axis attention: per (b,v). Channels: q 96..111, k 112..127, v 128..191. (R2 verbatim)
// ---------------------------------------------------------------------------
__global__ __launch_bounds__(256) void attnT_kernel()
{
    extern __shared__ float sm[];
    float* Qs = sm;                 // 16*128
    float* Ks = Qs + 16*128;        // 16*128
    float* Vs = Ks + 16*128;        // 64*128
    float* L  = Vs + 64*128;        // 128*129
    const int b = blockIdx.x >> 6, v = blockIdx.x & 63;
    const int tid = threadIdx.x;
    const float* base = g_buf1 + (size_t)b * 192 * SP + (size_t)v * TT;

    for (int idx = tid; idx < 16*128; idx += 256) {
        int c = idx >> 7, t = idx & 127;
        Qs[idx] = base[(size_t)(96 + c)*SP + t];
        Ks[idx] = base[(size_t)(112 + c)*SP + t];
    }
    for (int idx = tid; idx < 64*128; idx += 256) {
        int c = idx >> 7, t = idx & 127;
        Vs[idx] = base[(size_t)(128 + c)*SP + t];
    }
    __syncthreads();
    for (int idx = tid; idx < 128*128; idx += 256) {
        int t = idx >> 7, s0 = idx & 127;
        float s = 0.f;
        #pragma unroll
        for (int c = 0; c < 16; c++) s += Qs[c*128 + t]*Ks[c*128 + s0];
        L[t*129 + s0] = s;
    }
    __syncthreads();
    if (tid < 128) {
        float* row = L + tid*129;
        float m = -1e30f;
        for (int s0 = 0; s0 < 128; s0++) m = fmaxf(m, row[s0]);
        float sum = 0.f;
        for (int s0 = 0; s0 < 128; s0++) { float e = __expf(row[s0]-m); row[s0] = e; sum += e; }
        float inv = 1.f/sum;
        for (int s0 = 0; s0 < 128; s0++) row[s0] *= inv;
    }
    __syncthreads();
    float* avb = g_av + (size_t)b * CC * SP + (size_t)64 * SP + (size_t)v * TT;
    for (int idx = tid; idx < 64*128; idx += 256) {
        int c = idx >> 7, t = idx & 127;
        float s = 0.f;
        #pragma unroll
        for (int s0 = 0; s0 < 128; s0++) s += L[t*129 + s0]*Vs[c*128 + s0];
        avb[(size_t)c*SP + t] = s;
    }
}

// ---------------------------------------------------------------------------
// SE (R2 verbatim)
// ---------------------------------------------------------------------------
__global__ __launch_bounds__(256) void se_mean_kernel(const float* __restrict__ x)
{
    __shared__ float red[256];
    const int bc = blockIdx.x;
    const float* p = x + (size_t)bc * SP;
    float s = 0.f;
    for (int i = threadIdx.x; i < SP; i += 256) s += p[i];
    red[threadIdx.x] = s; __syncthreads();
    for (int off = 128; off > 0; off >>= 1) {
        if (threadIdx.x < off) red[threadIdx.x] += red[threadIdx.x + off];
        __syncthreads();
    }
    if (threadIdx.x == 0) g_mean[bc] = red[0] * (1.f / SP);
}

__global__ __launch_bounds__(128) void se_mlp_kernel(
    const float* __restrict__ w1, const float* __restrict__ w2)
{
    __shared__ float ym[128];
    __shared__ float h[8];
    const int b = blockIdx.x, tid = threadIdx.x;
    ym[tid] = g_mean[b*128 + tid];
    __syncthreads();
    if (tid < 8) {
        float s = 0.f;
        for (int c = 0; c < 128; c++) s += ym[c]*w1[tid*128 + c];
        h[tid] = s > 0.f ? s : 0.f;
    }
    __syncthreads();
    float s = 0.f;
    #pragma unroll
    for (int r = 0; r < 8; r++) s += h[r]*w2[tid*8 + r];
    g_scale[b*128 + tid] = 1.f/(1.f + expf(-s));
}

// ---------------------------------------------------------------------------
extern "C" void kernel_launch(void* const* d_in, const int* in_sizes, int n_in,
                              void* d_out, int out_size)
{
    const float* x     = (const float*)d_in[0];
    const float* v_qw  = (const float*)d_in[1];
    const float* v_kw  = (const float*)d_in[2];
    const float* v_vw  = (const float*)d_in[3];
    const float* v_ow  = (const float*)d_in[4];
    const float* v_sig = (const float*)d_in[5];
    const float* t_qw  = (const float*)d_in[6];
    const float* t_kw  = (const float*)d_in[7];
    const float* t_vw  = (const float*)d_in[8];
    const float* t_ow  = (const float*)d_in[9];
    const float* t_sig = (const float*)d_in[10];
    const float* se_w1 = (const float*)d_in[11];
    const float* se_w2 = (const float*)d_in[12];
    float* out = (float*)d_out;

    const int attnT_smem = (16*128 + 16*128 + 64*128 + 128*129) * 4; // 115200 B
    cudaFuncSetAttribute(attnT_kernel, cudaFuncAttributeMaxDynamicSharedMemorySize, attnT_smem);

    // weight pre-conversion
    wcvt1_kernel<<<(8*9*192*12 + 255)/256, 256>>>(v_qw, v_kw, v_vw, t_qw, t_kw, t_vw);
    wcvt2_kernel<<<(8*9*128*12 + 255)/256, 256>>>(v_ow, t_ow, v_sig, t_sig);

    // SE path (independent)
    se_mean_kernel<<<BB*CC, 256>>>(x);
    se_mlp_kernel<<<BB, 128>>>(se_w1, se_w2);

    conv1_mma_kernel<<<dim3(64, 32, 3), 256>>>(x);
    attnV_kernel<<<BB*TT, 256>>>();
    attnT_kernel<<<BB*VV, 256, attnT_smem>>>();
    conv2_mma_kernel<<<dim3(64, 32, 2), 256>>>(x, out);
}

// round 6
// speedup vs baseline: 4.4478x; 1.1228x over previous
#include <cuda_runtime.h>
#include <cuda_bf16.h>
#include <math.h>
#include <stdint.h>

#define BB 32
#define CC 128
#define VV 64
#define TT 128
#define SP (VV*TT)   // 8192

// ---------------------------------------------------------------------------
// Scratch (device globals). ~369 MiB total; every kernel kept spill-free.
// ---------------------------------------------------------------------------
__device__ float g_buf1[(size_t)BB * 192 * SP]; // conv1 out [b][c][v][t]  192 MiB
__device__ float g_av [(size_t)BB * CC  * SP];  // [av_v 64 | av_t 64]     128 MiB
__device__ __nv_bfloat16 g_bufT[(size_t)BB * TT * 96 * VV]; // [b][t][c][v] 48 MiB (attnV in; av out in-place)
__device__ float g_mean [BB * CC];
__device__ float g_scale[BB * CC];
// packed bf16 weights: [chunk8][tap9][co][12 words] (words 0..7 = ci-pairs, 8..11 pad)
__device__ uint32_t g_w1[8 * 9 * 192 * 12];
__device__ uint32_t g_w2[8 * 9 * 128 * 12];

// ---------------------------------------------------------------------------
__device__ __forceinline__ uint32_t pack_bf16(float a, float b) {
    __nv_bfloat16 lo = __float2bfloat16(a), hi = __float2bfloat16(b);
    return ((uint32_t)__bfloat16_as_ushort(hi) << 16) | (uint32_t)__bfloat16_as_ushort(lo);
}

__device__ __forceinline__ void mma_bf16(
    float& d0, float& d1, float& d2, float& d3,
    uint32_t a0, uint32_t a1, uint32_t a2, uint32_t a3,
    uint32_t b0, uint32_t b1)
{
    asm volatile(
        "mma.sync.aligned.m16n8k16.row.col.f32.bf16.bf16.f32 "
        "{%0,%1,%2,%3}, {%4,%5,%6,%7}, {%8,%9}, {%0,%1,%2,%3};"
        : "+f"(d0), "+f"(d1), "+f"(d2), "+f"(d3)
        : "r"(a0), "r"(a1), "r"(a2), "r"(a3), "r"(b0), "r"(b1));
}

// ---------------------------------------------------------------------------
// Weight pre-conversion kernels
// ---------------------------------------------------------------------------
__global__ __launch_bounds__(256) void wcvt1_kernel(
    const float* __restrict__ v_qw, const float* __restrict__ v_kw,
    const float* __restrict__ v_vw,
    const float* __restrict__ t_qw, const float* __restrict__ t_kw,
    const float* __restrict__ t_vw)
{
    int idx = blockIdx.x * 256 + threadIdx.x;
    if (idx >= 8*9*192*12) return;
    int w    = idx % 12;
    int co   = (idx / 12) % 192;
    int tap  = (idx / (12*192)) % 9;
    int chunk= idx / (12*192*9);
    uint32_t val = 0;
    if (w < 8) {
        int ci = chunk*16 + w*2;
        const float* wb; int coL;
        if      (co < 16)  { wb = v_qw; coL = co;       }
        else if (co < 32)  { wb = v_kw; coL = co - 16;  }
        else if (co < 96)  { wb = v_vw; coL = co - 32;  }
        else if (co < 112) { wb = t_qw; coL = co - 96;  }
        else if (co < 128) { wb = t_kw; coL = co - 112; }
        else               { wb = t_vw; coL = co - 128; }
        float f0 = wb[(coL*CC + ci    )*9 + tap];
        float f1 = wb[(coL*CC + ci + 1)*9 + tap];
        val = pack_bf16(f0, f1);
    }
    g_w1[idx] = val;
}

__global__ __launch_bounds__(256) void wcvt2_kernel(
    const float* __restrict__ v_ow, const float* __restrict__ t_ow,
    const float* __restrict__ v_sigma, const float* __restrict__ t_sigma)
{
    int idx = blockIdx.x * 256 + threadIdx.x;
    if (idx >= 8*9*128*12) return;
    int w    = idx % 12;
    int co   = (idx / 12) % 128;
    int tap  = (idx / (12*128)) % 9;
    int chunk= idx / (12*128*9);
    uint32_t val = 0;
    if (w < 8) {
        int ci = chunk*16 + w*2;
        float f0, f1;
        if (ci < 64) {
            float s = v_sigma[0];
            f0 = v_ow[(co*64 + ci    )*9 + tap] * s;
            f1 = v_ow[(co*64 + ci + 1)*9 + tap] * s;
        } else {
            float s = t_sigma[0];
            f0 = t_ow[(co*64 + (ci-64))*9 + tap] * s;
            f1 = t_ow[(co*64 + (ci-63))*9 + tap] * s;
        }
        val = pack_bf16(f0, f1);
    }
    g_w2[idx] = val;
}

// ---------------------------------------------------------------------------
// bf16 implicit-GEMM conv core (R5-proven geometry, unchanged).
// ---------------------------------------------------------------------------
__device__ __forceinline__ void conv_core_f(
    const float* __restrict__ src,
    const uint32_t* __restrict__ gw,
    int CO_TOT,
    int b, int co0, int v0, int t0,
    float acc[2][4][4])
{
    __shared__ uint32_t xs[6*34*12];
    __shared__ uint32_t ws[9*64*12];

    const int tid  = threadIdx.x;
    const int lane = tid & 31;
    const int warp = tid >> 5;
    const int g  = lane >> 2;
    const int k4 = lane & 3;
    const int wm = warp >> 2;
    const int wn = warp & 3;

    #pragma unroll
    for (int mt = 0; mt < 2; mt++)
        #pragma unroll
        for (int nt = 0; nt < 4; nt++)
            #pragma unroll
            for (int r = 0; r < 4; r++) acc[mt][nt][r] = 0.f;

    for (int chunk = 0; chunk < 8; chunk++) {
        for (int idx = tid; idx < 1632; idx += 256) {
            int v   = idx / 272;
            int rem = idx % 272;
            int cp  = rem / 34;
            int t   = rem % 34;
            int gv = v0 - 1 + v, gt = t0 - 1 + t;
            int ci = chunk*16 + cp*2;
            uint32_t val = 0;
            if (gv >= 0 && gv < VV && gt >= 0 && gt < TT) {
                const float* p = src + (((size_t)b*CC + ci)*VV + gv)*TT + gt;
                val = pack_bf16(p[0], p[SP]);
            }
            xs[(v*34 + t)*12 + cp] = val;
        }
        {
            const uint4* src4 = (const uint4*)gw;
            uint4* dst4 = (uint4*)ws;
            for (int idx = tid; idx < 1728; idx += 256) {
                int tap = idx / 192;
                int w4  = idx % 192;
                dst4[tap*192 + w4] = src4[(size_t)((chunk*9 + tap)*CO_TOT + co0)*3 + w4];
            }
        }
        __syncthreads();

        #pragma unroll
        for (int kh = 0; kh < 3; kh++) {
            #pragma unroll
            for (int kw = 0; kw < 3; kw++) {
                const int tap = kh*3 + kw;
                const uint32_t* wt = ws + tap*768;
                uint32_t a0[2], a1[2], a2[2], a3[2];
                #pragma unroll
                for (int mt = 0; mt < 2; mt++) {
                    const uint32_t* p = wt + (wm*32 + mt*16 + g) * 12;
                    a0[mt] = p[k4];
                    a2[mt] = p[k4+4];
                    a1[mt] = p[96 + k4];
                    a3[mt] = p[96 + k4+4];
                }
                const uint32_t* xrow = xs + ((wn + kh)*34 + g + kw) * 12;
                #pragma unroll
                for (int nt = 0; nt < 4; nt++) {
                    const uint32_t* xr = xrow + nt*96;
                    uint32_t b0 = xr[k4];
                    uint32_t b1 = xr[k4+4];
                    #pragma unroll
                    for (int mt = 0; mt < 2; mt++)
                        mma_bf16(acc[mt][nt][0], acc[mt][nt][1],
                                 acc[mt][nt][2], acc[mt][nt][3],
                                 a0[mt], a1[mt], a2[mt], a3[mt], b0, b1);
                }
            }
        }
        __syncthreads();
    }
}

// ---------------------------------------------------------------------------
__global__ __launch_bounds__(256) void conv1_mma_kernel(const float* __restrict__ x)
{
    const int tile = blockIdx.x;
    const int b = blockIdx.y;
    const int co0 = blockIdx.z * 64;
    const int v0 = (tile >> 2) * 4;
    const int t0 = (tile & 3) * 32;

    float acc[2][4][4];
    conv_core_f(x, g_w1, 192, b, co0, v0, t0, acc);

    const int lane = threadIdx.x & 31;
    const int warp = threadIdx.x >> 5;
    const int g  = lane >> 2;
    const int k4 = lane & 3;
    const int wm = warp >> 2;
    const int wn = warp & 3;
    const int v = v0 + wn;

    #pragma unroll
    for (int mt = 0; mt < 2; mt++) {
        #pragma unroll
        for (int nt = 0; nt < 4; nt++) {
            int coA = co0 + wm*32 + mt*16 + g;
            int coB = coA + 8;
            int t = t0 + nt*8 + k4*2;
            bool tA = (coA < 32) || (coA >= 96 && coA < 128);
            bool tB = (coB < 32) || (coB >= 96 && coB < 128);
            float r0 = acc[mt][nt][0], r1 = acc[mt][nt][1];
            float r2 = acc[mt][nt][2], r3 = acc[mt][nt][3];
            if (tA) { r0 = tanhf(r0); r1 = tanhf(r1); }
            if (tB) { r2 = tanhf(r2); r3 = tanhf(r3); }
            *(float2*)&g_buf1[(((size_t)b*192 + coA)*VV + v)*TT + t] = make_float2(r0, r1);
            *(float2*)&g_buf1[(((size_t)b*192 + coB)*VV + v)*TT + t] = make_float2(r2, r3);
        }
    }
}

__global__ __launch_bounds__(256) void conv2_mma_kernel(
    const float* __restrict__ x, float* __restrict__ out)
{
    const int tile = blockIdx.x;
    const int b = blockIdx.y;
    const int co0 = blockIdx.z * 64;
    const int v0 = (tile >> 2) * 4;
    const int t0 = (tile & 3) * 32;

    float acc[2][4][4];
    conv_core_f(g_av, g_w2, 128, b, co0, v0, t0, acc);

    const int lane = threadIdx.x & 31;
    const int warp = threadIdx.x >> 5;
    const int g  = lane >> 2;
    const int k4 = lane & 3;
    const int wm = warp >> 2;
    const int wn = warp & 3;
    const int v = v0 + wn;

    #pragma unroll
    for (int mt = 0; mt < 2; mt++) {
        #pragma unroll
        for (int nt = 0; nt < 4; nt++) {
            int coA = co0 + wm*32 + mt*16 + g;
            int coB = coA + 8;
            int t = t0 + nt*8 + k4*2;
            size_t iA = (((size_t)b*CC + coA)*VV + v)*TT + t;
            size_t iB = (((size_t)b*CC + coB)*VV + v)*TT + t;
            float2 xA = *(const float2*)&x[iA];
            float2 xB = *(const float2*)&x[iB];
            float sA = g_scale[b*CC + coA];
            float sB = g_scale[b*CC + coB];
            *(float2*)&out[iA] = make_float2((xA.x + acc[mt][nt][0])*sA,
                                             (xA.y + acc[mt][nt][1])*sA);
            *(float2*)&out[iB] = make_float2((xB.x + acc[mt][nt][2])*sB,
                                             (xB.y + acc[mt][nt][3])*sB);
        }
    }
}

// ---------------------------------------------------------------------------
// t1: per b, transpose g_buf1 [6144 cv][128 t] (fp32) -> g_bufT [128 t][6144 cv] (bf16)
// ---------------------------------------------------------------------------
__global__ __launch_bounds__(256) void t1_kernel()
{
    __shared__ float tl[32][33];
    const int b = blockIdx.z;
    const float* ip = g_buf1 + (size_t)b * 192 * SP;
    __nv_bfloat16* op = g_bufT + (size_t)b * TT * 96 * 64;
    const int r0 = blockIdx.y * 32;   // cv
    const int c0 = blockIdx.x * 32;   // t
    const int tx = threadIdx.x & 31, ty = threadIdx.x >> 5;
    #pragma unroll
    for (int i = 0; i < 4; i++)
        tl[ty + i*8][tx] = ip[(size_t)(r0 + ty + i*8)*128 + c0 + tx];
    __syncthreads();
    #pragma unroll
    for (int i = 0; i < 4; i++)
        op[(size_t)(c0 + ty + i*8)*6144 + r0 + tx] = __float2bfloat16(tl[tx][ty + i*8]);
}

// ---------------------------------------------------------------------------
// t2: per b, transpose g_bufT [128 t][4096 cv (row stride 6144)] (bf16)
//     -> g_av v-path half [4096 cv][128 t] (fp32)
// ---------------------------------------------------------------------------
__global__ __launch_bounds__(256) void t2_kernel()
{
    __shared__ float tl[32][33];
    const int b = blockIdx.z;
    const __nv_bfloat16* ip = g_bufT + (size_t)b * TT * 96 * 64;
    float* op = g_av + (size_t)b * CC * SP;
    const int r0 = blockIdx.y * 32;   // t
    const int c0 = blockIdx.x * 32;   // cv
    const int tx = threadIdx.x & 31, ty = threadIdx.x >> 5;
    #pragma unroll
    for (int i = 0; i < 4; i++)
        tl[ty + i*8][tx] = __bfloat162float(ip[(size_t)(r0 + ty + i*8)*6144 + c0 + tx]);
    __syncthreads();
    #pragma unroll
    for (int i = 0; i < 4; i++)
        op[(size_t)(c0 + ty + i*8)*128 + r0 + tx] = tl[tx][ty + i*8];
}

// ---------------------------------------------------------------------------
// V-axis attention. Per (b,t). Coalesced bf16 loads; 4x4 register tiles;
// writes av in-place (first 64x64 of the slice).
// ---------------------------------------------------------------------------
__global__ __launch_bounds__(256) void attnV_kernel()
{
    __shared__ float Qs[16][65], Ks[16][65], Vs[64][65], L[64][65];
    const int b = blockIdx.x >> 7, t = blockIdx.x & 127;
    const int tid = threadIdx.x;
    const __nv_bfloat16* base = g_bufT + ((size_t)(b*TT + t)) * 96 * 64;

    for (int idx = tid; idx < 16*64; idx += 256) {
        int c = idx >> 6, v = idx & 63;
        Qs[c][v] = __bfloat162float(base[idx]);
        Ks[c][v] = __bfloat162float(base[16*64 + idx]);
    }
    for (int idx = tid; idx < 64*64; idx += 256) {
        int c = idx >> 6, v = idx & 63;
        Vs[c][v] = __bfloat162float(base[32*64 + idx]);
    }
    __syncthreads();

    // logits 64x64, 4x4 per thread
    {
        int w4 = (tid & 15) * 4, v4 = (tid >> 4) * 4;
        float l[4][4];
        #pragma unroll
        for (int i = 0; i < 4; i++)
            #pragma unroll
            for (int j = 0; j < 4; j++) l[i][j] = 0.f;
        #pragma unroll
        for (int c = 0; c < 16; c++) {
            float q[4], k[4];
            #pragma unroll
            for (int i = 0; i < 4; i++) q[i] = Qs[c][v4+i];
            #pragma unroll
            for (int j = 0; j < 4; j++) k[j] = Ks[c][w4+j];
            #pragma unroll
            for (int i = 0; i < 4; i++)
                #pragma unroll
                for (int j = 0; j < 4; j++) l[i][j] = fmaf(q[i], k[j], l[i][j]);
        }
        #pragma unroll
        for (int i = 0; i < 4; i++)
            #pragma unroll
            for (int j = 0; j < 4; j++) L[v4+i][w4+j] = l[i][j];
    }
    __syncthreads();

    // softmax over w, 4 threads per row
    {
        int row = tid >> 2, q = tid & 3;
        float m = -1e30f;
        #pragma unroll
        for (int j = 0; j < 16; j++) m = fmaxf(m, L[row][q*16 + j]);
        m = fmaxf(m, __shfl_xor_sync(0xffffffffu, m, 1));
        m = fmaxf(m, __shfl_xor_sync(0xffffffffu, m, 2));
        float s = 0.f;
        #pragma unroll
        for (int j = 0; j < 16; j++) {
            float e = __expf(L[row][q*16 + j] - m);
            L[row][q*16 + j] = e;
            s += e;
        }
        s += __shfl_xor_sync(0xffffffffu, s, 1);
        s += __shfl_xor_sync(0xffffffffu, s, 2);
        float inv = 1.f / s;
        #pragma unroll
        for (int j = 0; j < 16; j++) L[row][q*16 + j] *= inv;
    }
    __syncthreads();

    // av[c][v] = sum_w L[v][w] * Vs[c][w]; in-place bf16 store
    {
        int c4 = (tid & 15) * 4, v4 = (tid >> 4) * 4;
        float o[4][4];
        #pragma unroll
        for (int j = 0; j < 4; j++)
            #pragma unroll
            for (int i = 0; i < 4; i++) o[j][i] = 0.f;
        for (int w = 0; w < 64; w++) {
            float a[4], vv[4];
            #pragma unroll
            for (int i = 0; i < 4; i++) a[i] = L[v4+i][w];
            #pragma unroll
            for (int j = 0; j < 4; j++) vv[j] = Vs[c4+j][w];
            #pragma unroll
            for (int j = 0; j < 4; j++)
                #pragma unroll
                for (int i = 0; i < 4; i++) o[j][i] = fmaf(vv[j], a[i], o[j][i]);
        }
        __nv_bfloat16* outb = g_bufT + ((size_t)(b*TT + t)) * 96 * 64;
        #pragma unroll
        for (int j = 0; j < 4; j++) {
            __nv_bfloat162 p0, p1;
            p0.x = __float2bfloat16(o[j][0]); p0.y = __float2bfloat16(o[j][1]);
            p1.x = __float2bfloat16(o[j][2]); p1.y = __float2bfloat16(o[j][3]);
            *(__nv_bfloat162*)&outb[(c4+j)*64 + v4    ] = p0;
            *(__nv_bfloat162*)&outb[(c4+j)*64 + v4 + 2] = p1;
        }
    }
}

// ---------------------------------------------------------------------------
// T-axis attention. Per (b,v). fp32, coalesced loads, 4x4 register tiles.
// ---------------------------------------------------------------------------
__global__ __launch_bounds__(256) void attnT_kernel()
{
    extern __shared__ float sm[];
    float* Qs = sm;                       // [16][129]
    float* Ks = Qs + 16*129;              // [16][129]
    float* Vs = Ks + 16*129;              // [64][129]
    float* L  = Vs + 64*129;              // [128][129]
    const int b = blockIdx.x >> 6, v = blockIdx.x & 63;
    const int tid = threadIdx.x;
    const float* base = g_buf1 + (size_t)b * 192 * SP + (size_t)v * TT;

    for (int idx = tid; idx < 16*128; idx += 256) {
        int c = idx >> 7, t = idx & 127;
        Qs[c*129 + t] = base[(size_t)(96 + c)*SP + t];
        Ks[c*129 + t] = base[(size_t)(112 + c)*SP + t];
    }
    for (int idx = tid; idx < 64*128; idx += 256) {
        int c = idx >> 7, t = idx & 127;
        Vs[c*129 + t] = base[(size_t)(128 + c)*SP + t];
    }
    __syncthreads();

    // logits 128x128, 4x4 tiles, 2x2 reps
    #pragma unroll
    for (int rt = 0; rt < 2; rt++) {
        #pragma unroll
        for (int rs = 0; rs < 2; rs++) {
            int t4 = (tid >> 4)*4 + rt*64;
            int s4 = (tid & 15)*4 + rs*64;
            float l[4][4];
            #pragma unroll
            for (int i = 0; i < 4; i++)
                #pragma unroll
                for (int j = 0; j < 4; j++) l[i][j] = 0.f;
            #pragma unroll
            for (int c = 0; c < 16; c++) {
                float q[4], k[4];
                #pragma unroll
                for (int i = 0; i < 4; i++) q[i] = Qs[c*129 + t4+i];
                #pragma unroll
                for (int j = 0; j < 4; j++) k[j] = Ks[c*129 + s4+j];
                #pragma unroll
                for (int i = 0; i < 4; i++)
                    #pragma unroll
                    for (int j = 0; j < 4; j++) l[i][j] = fmaf(q[i], k[j], l[i][j]);
            }
            #pragma unroll
            for (int i = 0; i < 4; i++)
                #pragma unroll
                for (int j = 0; j < 4; j++) L[(t4+i)*129 + s4+j] = l[i][j];
        }
    }
    __syncthreads();

    // softmax over s, 2 threads per row
    {
        int row = tid >> 1, q = tid & 1;
        float* rp = L + row*129 + q*64;
        float m = -1e30f;
        #pragma unroll
        for (int j = 0; j < 64; j++) m = fmaxf(m, rp[j]);
        m = fmaxf(m, __shfl_xor_sync(0xffffffffu, m, 1));
        float s = 0.f;
        #pragma unroll
        for (int j = 0; j < 64; j++) { float e = __expf(rp[j] - m); rp[j] = e; s += e; }
        s += __shfl_xor_sync(0xffffffffu, s, 1);
        float inv = 1.f / s;
        #pragma unroll
        for (int j = 0; j < 64; j++) rp[j] *= inv;
    }
    __syncthreads();

    // av[c][t] = sum_s L[t][s] * Vs[c][s]
    float* avb = g_av + (size_t)b * CC * SP + (size_t)64 * SP + (size_t)v * TT;
    #pragma unroll
    for (int rt = 0; rt < 2; rt++) {
        int c4 = (tid & 15)*4;
        int t4 = (tid >> 4)*4 + rt*64;
        float o[4][4];
        #pragma unroll
        for (int j = 0; j < 4; j++)
            #pragma unroll
            for (int i = 0; i < 4; i++) o[j][i] = 0.f;
        for (int s = 0; s < 128; s++) {
            float a[4], vv[4];
            #pragma unroll
            for (int i = 0; i < 4; i++) a[i] = L[(t4+i)*129 + s];
            #pragma unroll
            for (int j = 0; j < 4; j++) vv[j] = Vs[(c4+j)*129 + s];
            #pragma unroll
            for (int j = 0; j < 4; j++)
                #pragma unroll
                for (int i = 0; i < 4; i++) o[j][i] = fmaf(vv[j], a[i], o[j][i]);
        }
        #pragma unroll
        for (int j = 0; j < 4; j++) {
            *(float4*)&avb[(size_t)(c4+j)*SP + t4] =
                make_float4(o[j][0], o[j][1], o[j][2], o[j][3]);
        }
    }
}

// ---------------------------------------------------------------------------
// SE
// ---------------------------------------------------------------------------
__global__ __launch_bounds__(256) void se_mean_kernel(const float* __restrict__ x)
{
    __shared__ float red[256];
    const int bc = blockIdx.x;
    const float4* p = (const float4*)(x + (size_t)bc * SP);
    float s = 0.f;
    for (int i = threadIdx.x; i < SP/4; i += 256) {
        float4 f = p[i];
        s += f.x + f.y + f.z + f.w;
    }
    red[threadIdx.x] = s; __syncthreads();
    for (int off = 128; off > 0; off >>= 1) {
        if (threadIdx.x < off) red[threadIdx.x] += red[threadIdx.x + off];
        __syncthreads();
    }
    if (threadIdx.x == 0) g_mean[bc] = red[0] * (1.f / SP);
}

__global__ __launch_bounds__(128) void se_mlp_kernel(
    const float* __restrict__ w1, const float* __restrict__ w2)
{
    __shared__ float ym[128];
    __shared__ float h[8];
    const int b = blockIdx.x, tid = threadIdx.x;
    ym[tid] = g_mean[b*128 + tid];
    __syncthreads();
    if (tid < 8) {
        float s = 0.f;
        for (int c = 0; c < 128; c++) s += ym[c]*w1[tid*128 + c];
        h[tid] = s > 0.f ? s : 0.f;
    }
    __syncthreads();
    float s = 0.f;
    #pragma unroll
    for (int r = 0; r < 8; r++) s += h[r]*w2[tid*8 + r];
    g_scale[b*128 + tid] = 1.f/(1.f + expf(-s));
}

// ---------------------------------------------------------------------------
extern "C" void kernel_launch(void* const* d_in, const int* in_sizes, int n_in,
                              void* d_out, int out_size)
{
    const float* x     = (const float*)d_in[0];
    const float* v_qw  = (const float*)d_in[1];
    const float* v_kw  = (const float*)d_in[2];
    const float* v_vw  = (const float*)d_in[3];
    const float* v_ow  = (const float*)d_in[4];
    const float* v_sig = (const float*)d_in[5];
    const float* t_qw  = (const float*)d_in[6];
    const float* t_kw  = (const float*)d_in[7];
    const float* t_vw  = (const float*)d_in[8];
    const float* t_ow  = (const float*)d_in[9];
    const float* t_sig = (const float*)d_in[10];
    const float* se_w1 = (const float*)d_in[11];
    const float* se_w2 = (const float*)d_in[12];
    float* out = (float*)d_out;

    const int attnT_smem = (16*129 + 16*129 + 64*129 + 128*129) * 4; // 115584 B
    cudaFuncSetAttribute(attnT_kernel, cudaFuncAttributeMaxDynamicSharedMemorySize, attnT_smem);

    // weight pre-conversion
    wcvt1_kernel<<<(8*9*192*12 + 255)/256, 256>>>(v_qw, v_kw, v_vw, t_qw, t_kw, t_vw);
    wcvt2_kernel<<<(8*9*128*12 + 255)/256, 256>>>(v_ow, t_ow, v_sig, t_sig);

    // SE path (independent)
    se_mean_kernel<<<BB*CC, 256>>>(x);
    se_mlp_kernel<<<BB, 128>>>(se_w1, se_w2);

    conv1_mma_kernel<<<dim3(64, 32, 3), 256>>>(x);

    // v-path qkv -> [b][t][c][v] bf16
    t1_kernel<<<dim3(4, 192, BB), 256>>>();
    attnV_kernel<<<BB*TT, 256>>>();
    // attnV out -> g_av v-path half (fp32, [b][c][v][t])
    t2_kernel<<<dim3(128, 4, BB), 256>>>();

    attnT_kernel<<<BB*VV, 256, attnT_smem>>>();

    conv2_mma_kernel<<<dim3(64, 32, 2), 256>>>(x, out);
}